// round 5
// baseline (speedup 1.0000x reference)
#include <cuda_runtime.h>
#include <cuda_bf16.h>
#include <math.h>
#include <stdint.h>

#define BB  8
#define DIM 128
#define CL  32
#define HH  256
#define WW  256

#define APITCH 136            // bf16 elems per row (K padded)
#define APB    (APITCH*2)     // 272 bytes, 16B-aligned rows, conflict-free for ldmatrix

// ---------------- device scratch ----------------
__device__ float g_S0[BB*CL*HH*WW];
__device__ float g_P1[BB*CL*128*128];
__device__ float g_D1[BB*CL*128*128];
__device__ float g_P2[BB*CL*64*64];
__device__ float g_D2[BB*CL*64*64];
__device__ float g_P3[BB*CL*32*32];
__device__ float g_D3[BB*CL*32*32];

// weight images: shuffle-folded, bf16 hi/lo split, [N][APITCH]
__device__ __align__(16) __nv_bfloat16 g_W1h[64*APITCH];
__device__ __align__(16) __nv_bfloat16 g_W1l[64*APITCH];
__device__ __align__(16) __nv_bfloat16 g_W2h[96*APITCH];
__device__ __align__(16) __nv_bfloat16 g_W2l[96*APITCH];
__device__ __align__(16) __nv_bfloat16 g_W3h[128*APITCH];
__device__ __align__(16) __nv_bfloat16 g_W3l[128*APITCH];

// ---------------- smem byte offsets (fused kernel) ----------------
#define OFF_AHI 0
#define OFF_ALO 34816
#define OFF_W1H 69632
#define OFF_W1L 87040
#define OFF_W2H 104448
#define OFF_W2L 130560
#define OFF_W3H 156672
#define OFF_W3L 191488
#define SMEM_REQ 226304

// ---------------- asm helpers ----------------
__device__ __forceinline__ uint32_t smem_u32(const void* p) {
    uint32_t a;
    asm("{ .reg .u64 t; cvta.to.shared.u64 t, %1; cvt.u32.u64 %0, t; }" : "=r"(a) : "l"(p));
    return a;
}
__device__ __forceinline__ void ldsm_x4(uint32_t r[4], uint32_t addr) {
    asm volatile("ldmatrix.sync.aligned.m8n8.x4.shared.b16 {%0,%1,%2,%3}, [%4];"
        : "=r"(r[0]), "=r"(r[1]), "=r"(r[2]), "=r"(r[3]) : "r"(addr));
}
__device__ __forceinline__ void ldsm_x2(uint32_t& r0, uint32_t& r1, uint32_t addr) {
    asm volatile("ldmatrix.sync.aligned.m8n8.x2.shared.b16 {%0,%1}, [%2];"
        : "=r"(r0), "=r"(r1) : "r"(addr));
}
__device__ __forceinline__ void mma16816(float d[4], const uint32_t a[4], uint32_t b0, uint32_t b1) {
    asm volatile("mma.sync.aligned.m16n8k16.row.col.f32.bf16.bf16.f32 "
        "{%0,%1,%2,%3}, {%4,%5,%6,%7}, {%8,%9}, {%0,%1,%2,%3};"
        : "+f"(d[0]), "+f"(d[1]), "+f"(d[2]), "+f"(d[3])
        : "r"(a[0]), "r"(a[1]), "r"(a[2]), "r"(a[3]), "r"(b0), "r"(b1));
}
__device__ __forceinline__ void sts16(uint32_t addr, uint16_t v) {
    asm volatile("st.shared.b16 [%0], %1;" :: "r"(addr), "h"(v) : "memory");
}
__device__ __forceinline__ void sts32(uint32_t addr, uint32_t v) {
    asm volatile("st.shared.b32 [%0], %1;" :: "r"(addr), "r"(v) : "memory");
}
__device__ __forceinline__ void lds128(float& a, float& b, float& c, float& d, uint32_t addr) {
    asm volatile("ld.shared.v4.f32 {%0,%1,%2,%3}, [%4];"
        : "=f"(a), "=f"(b), "=f"(c), "=f"(d) : "r"(addr));
}
__device__ __forceinline__ void splitf(float v, uint16_t& h, uint16_t& l) {
    __nv_bfloat16 hb = __float2bfloat16(v);
    __nv_bfloat16 lb = __float2bfloat16(v - __bfloat162float(hb));
    h = __bfloat16_as_ushort(hb);
    l = __bfloat16_as_ushort(lb);
}

// ---------------- weight prep ----------------
__global__ void k_prep(const float* __restrict__ w1, const float* __restrict__ w2,
                       const float* __restrict__ w3)
{
    int t = blockIdx.x * blockDim.x + threadIdx.x;
    float w; __nv_bfloat16 *ph, *pl; int r, k;
    if (t < 64*64) {
        r = t >> 6; k = t & 63;
        w = w1[(r << 6) + ((k & 7) << 3) + (k >> 3)];
        ph = g_W1h; pl = g_W1l;
    } else if (t < 64*64 + 96*96) {
        int u = t - 64*64; r = u / 96; k = u % 96;
        w = w2[r*96 + (k % 12)*8 + k/12];
        ph = g_W2h; pl = g_W2l;
    } else if (t < 64*64 + 96*96 + 128*128) {
        int u = t - 64*64 - 96*96; r = u >> 7; k = u & 127;
        w = w3[(r << 7) + ((k & 15) << 3) + (k >> 4)];
        ph = g_W3h; pl = g_W3l;
    } else return;
    __nv_bfloat16 hb = __float2bfloat16(w);
    __nv_bfloat16 lb = __float2bfloat16(w - __bfloat162float(hb));
    ph[r*APITCH + k] = hb;
    pl[r*APITCH + k] = lb;
}

// ---------------- pools ----------------
template<int KK>
__device__ __forceinline__ void pool_impl(const float* __restrict__ x, int lvl,
                                          float* __restrict__ out)
{
    const int HO = HH / KK;
    int idx = blockIdx.x * blockDim.x + threadIdx.x;
    if (idx >= BB*CL*HO*HO) return;
    int xo = idx % HO;
    int yo = (idx / HO) % HO;
    int c  = (idx / (HO*HO)) % CL;
    int b  = idx / (HO*HO*CL);
    const float* p = x + (((size_t)b*DIM + lvl*CL + c)*HH + (size_t)yo*KK)*WW + (size_t)xo*KK;
    float m = -3.402823466e38f;
    #pragma unroll
    for (int dy = 0; dy < KK; dy++)
        #pragma unroll
        for (int dx = 0; dx < KK; dx++)
            m = fmaxf(m, p[dy*WW + dx]);
    out[idx] = m;
}
__global__ void k_pool2(const float* __restrict__ x){ pool_impl<2>(x, 1, g_P1); }
__global__ void k_pool4(const float* __restrict__ x){ pool_impl<4>(x, 2, g_P2); }
__global__ void k_pool8(const float* __restrict__ x){ pool_impl<8>(x, 3, g_P3); }

// ---------------- depthwise 3x3 (all levels in ONE kernel) ----------------
__device__ __forceinline__ void dw_one(const float* __restrict__ in, float* __restrict__ out,
                                       const float* __restrict__ w_dw, const float* __restrict__ b_dw,
                                       int lvl, int S, bool from_x, int idx)
{
    int xx = idx % S;
    int yy = (idx / S) % S;
    int c  = (idx / (S*S)) % CL;
    int b  = idx / (S*S*CL);
    const float* ip = from_x ? in + ((size_t)b*DIM + lvl*CL + c) * (size_t)(S*S)
                             : in + ((size_t)b*CL + c) * (size_t)(S*S);
    const float* wp = w_dw + (lvl*CL + c) * 9;
    float acc = b_dw[lvl*CL + c];
    #pragma unroll
    for (int ky = 0; ky < 3; ky++) {
        int iy = yy + ky - 1;
        if ((unsigned)iy >= (unsigned)S) continue;
        #pragma unroll
        for (int kx = 0; kx < 3; kx++) {
            int ix = xx + kx - 1;
            if ((unsigned)ix >= (unsigned)S) continue;
            acc = fmaf(wp[ky*3 + kx], ip[iy*S + ix], acc);
        }
    }
    out[idx] = acc;
}

#define N_DW0 (BB*CL*256*256)
#define N_DW1 (BB*CL*128*128)
#define N_DW2 (BB*CL*64*64)
#define N_DW3 (BB*CL*32*32)
__global__ void k_dwall(const float* __restrict__ x, const float* __restrict__ w,
                        const float* __restrict__ b)
{
    int idx = blockIdx.x * blockDim.x + threadIdx.x;
    if (idx < N_DW0) { dw_one(x, g_S0, w, b, 0, 256, true, idx); return; }
    idx -= N_DW0;
    if (idx < N_DW1) { dw_one(g_P1, g_D1, w, b, 1, 128, false, idx); return; }
    idx -= N_DW1;
    if (idx < N_DW2) { dw_one(g_P2, g_D2, w, b, 2, 64, false, idx); return; }
    idx -= N_DW2;
    if (idx < N_DW3) { dw_one(g_P3, g_D3, w, b, 3, 32, false, idx); return; }
}

// ---------------- GEMM stage (warp-level mma) ----------------
// 32 warps: grid 8(M) x 4(N). Warp tile: 16 pixels x NT*8 out channels.
template<int NT, int KT>
__device__ __forceinline__ void run_stage(uint32_t base, uint32_t WH, uint32_t WL,
                                          int wm, int wn, int lane, float acc[4][4])
{
    #pragma unroll
    for (int nt = 0; nt < NT; nt++)
        #pragma unroll
        for (int i = 0; i < 4; i++) acc[nt][i] = 0.0f;

    const int mbase = wm * 16;
    const int nbase = wn * NT * 8;
    const uint32_t a_off = (uint32_t)(mbase + (lane & 15)) * APB + ((lane >> 4) << 4);
    const uint32_t b_off = (uint32_t)(nbase + (lane & 7)) * APB + (((lane >> 3) & 1) << 4);
    const uint32_t AHI = base + OFF_AHI + a_off;
    const uint32_t ALO = base + OFF_ALO + a_off;

    #pragma unroll
    for (int kt = 0; kt < KT; kt++) {
        uint32_t ah[4], al[4];
        ldsm_x4(ah, AHI + kt*32);
        ldsm_x4(al, ALO + kt*32);
        #pragma unroll
        for (int nt = 0; nt < NT; nt++) {
            uint32_t bh0, bh1, bl0, bl1;
            ldsm_x2(bh0, bh1, WH + b_off + nt*8*APB + kt*32);
            ldsm_x2(bl0, bl1, WL + b_off + nt*8*APB + kt*32);
            mma16816(acc[nt], ah, bh0, bh1);
            mma16816(acc[nt], al, bh0, bh1);
            mma16816(acc[nt], ah, bl0, bl1);
        }
    }
}

template<int NT>
__device__ __forceinline__ void writeback(uint32_t base, const float* __restrict__ bias,
                                          int wm, int wn, int lane, float acc[4][4])
{
    const int mbase = wm * 16;
    const int nbase = wn * NT * 8;
    int p0 = mbase + (lane >> 2);
    #pragma unroll
    for (int nt = 0; nt < NT; nt++) {
        int o = nbase + nt*8 + (lane & 3)*2;
        float b0 = __ldg(&bias[o]), b1 = __ldg(&bias[o+1]);
        uint16_t h0, l0, h1, l1;
        splitf(acc[nt][0] + b0, h0, l0);
        splitf(acc[nt][1] + b1, h1, l1);
        uint32_t addr = base + (uint32_t)p0*APB + o*2;
        sts32(addr + OFF_AHI, (uint32_t)h0 | ((uint32_t)h1 << 16));
        sts32(addr + OFF_ALO, (uint32_t)l0 | ((uint32_t)l1 << 16));
        splitf(acc[nt][2] + b0, h0, l0);
        splitf(acc[nt][3] + b1, h1, l1);
        addr += 8*APB;
        sts32(addr + OFF_AHI, (uint32_t)h0 | ((uint32_t)h1 << 16));
        sts32(addr + OFF_ALO, (uint32_t)l0 | ((uint32_t)l1 << 16));
    }
}

// ---------------- fused kernel: 1024 threads, 32 warps ----------------
#define TPC 4
#define NTHR 1024
__global__ __launch_bounds__(NTHR, 1)
void fused_mma(const float* __restrict__ x,
               const float* __restrict__ bf1, const float* __restrict__ bf2,
               const float* __restrict__ bf3, float* __restrict__ out)
{
    extern __shared__ __align__(16) unsigned char sm[];
    const uint32_t base = smem_u32(sm);
    const int tid = threadIdx.x;
    const int lane = tid & 31, wid = tid >> 5;
    const int wm = wid >> 2, wn = wid & 3;

    // stage all weights once (156,672 B)
    {
        const __nv_bfloat16* gs[6] = { g_W1h, g_W1l, g_W2h, g_W2l, g_W3h, g_W3l };
        const int off[6] = { OFF_W1H, OFF_W1L, OFF_W2H, OFF_W2L, OFF_W3H, OFF_W3L };
        const int sz[6]  = { 17408, 17408, 26112, 26112, 34816, 34816 };
        #pragma unroll
        for (int a = 0; a < 6; a++) {
            const uint4* s4 = (const uint4*)gs[a];
            uint4* d4 = (uint4*)(sm + off[a]);
            for (int i = tid; i < sz[a]/16; i += NTHR) d4[i] = s4[i];
        }
    }

    float acc[4][4];

    for (int t = 0; t < TPC; t++) {
        int tile = blockIdx.x * TPC + t;
        int b = tile >> 9;
        int rem = (tile & 511) * 128;

        __syncthreads();

        // ---- build A (128 px x 128 ch, bf16 split) ----
        for (int i = tid; i < 128*128; i += NTHR) {
            int ch = i >> 7, p = i & 127;
            int r = rem + p;
            int y = r >> 8, xx = r & 255;
            float v;
            if (ch < 32)      v = g_S0[((b*32 + ch) << 16) + r];
            else if (ch < 64) v = g_D1[(b*32 + ch-32)*16384 + (y>>1)*128 + (xx>>1)];
            else if (ch < 96) v = g_D2[(b*32 + ch-64)*4096  + (y>>2)*64  + (xx>>2)];
            else              v = g_D3[(b*32 + ch-96)*1024  + (y>>3)*32  + (xx>>3)];
            uint16_t h, l;
            splitf(v, h, l);
            uint32_t addr = base + (uint32_t)p*APB + ch*2;
            sts16(addr + OFF_AHI, h);
            sts16(addr + OFF_ALO, l);
        }
        __syncthreads();

        // ---- stage 1 ----
        run_stage<2, 4>(base, base + OFF_W1H, base + OFF_W1L, wm, wn, lane, acc);
        __syncthreads();
        writeback<2>(base, bf1, wm, wn, lane, acc);
        __syncthreads();

        // ---- stage 2 ----
        run_stage<3, 6>(base, base + OFF_W2H, base + OFF_W2L, wm, wn, lane, acc);
        __syncthreads();
        writeback<3>(base, bf2, wm, wn, lane, acc);
        __syncthreads();

        // ---- stage 3 ----
        run_stage<4, 8>(base, base + OFF_W3H, base + OFF_W3L, wm, wn, lane, acc);
        __syncthreads();

        // ---- epilogue: gelu -> smem (stride 132 floats), coalesced *x -> out ----
        {
            const int mbase = wm * 16, nbase = wn * 32;
            int p0 = mbase + (lane >> 2);
            #pragma unroll
            for (int nt = 0; nt < 4; nt++) {
                int o = nbase + nt*8 + (lane & 3)*2;
                float b0 = __ldg(&bf3[o]), b1 = __ldg(&bf3[o+1]);
                #pragma unroll
                for (int hrow = 0; hrow < 2; hrow++) {
                    float v0 = acc[nt][2*hrow+0] + b0;
                    float v1 = acc[nt][2*hrow+1] + b1;
                    float g0 = 0.5f * v0 * (1.0f + erff(v0 * 0.70710678118654752f));
                    float g1 = 0.5f * v1 * (1.0f + erff(v1 * 0.70710678118654752f));
                    int p = p0 + hrow*8;
                    sts32(base + ((uint32_t)o    *132 + p)*4, __float_as_uint(g0));
                    sts32(base + ((uint32_t)(o+1)*132 + p)*4, __float_as_uint(g1));
                }
            }
        }
        __syncthreads();
        for (int i = tid; i < 128*32; i += NTHR) {
            int ch = i >> 5, g4 = (i & 31) * 4;
            size_t gi = ((size_t)(b*128 + ch) << 16) + rem + g4;
            float v0, v1, v2, v3;
            lds128(v0, v1, v2, v3, base + ((uint32_t)ch*132 + g4)*4);
            float4 xv = *(const float4*)&x[gi];
            float4 o4;
            o4.x = v0 * xv.x; o4.y = v1 * xv.y; o4.z = v2 * xv.z; o4.w = v3 * xv.w;
            *(float4*)&out[gi] = o4;
        }
    }
}

// ---------------- launch ----------------
extern "C" void kernel_launch(void* const* d_in, const int* in_sizes, int n_in,
                              void* d_out, int out_size)
{
    const float* x   = (const float*)d_in[0];
    const float* wdw = (const float*)d_in[1];
    const float* bdw = (const float*)d_in[2];
    const float* wf1 = (const float*)d_in[3];
    const float* bf1 = (const float*)d_in[4];
    const float* wf2 = (const float*)d_in[5];
    const float* bf2 = (const float*)d_in[6];
    const float* wf3 = (const float*)d_in[7];
    const float* bf3 = (const float*)d_in[8];
    float* out = (float*)d_out;
    (void)in_sizes; (void)n_in; (void)out_size;

    cudaFuncSetAttribute(fused_mma, cudaFuncAttributeMaxDynamicSharedMemorySize, SMEM_REQ);

    k_prep<<<(64*64 + 96*96 + 128*128 + 255)/256, 256>>>(wf1, wf2, wf3);     // 0
    k_pool2<<<(BB*CL*128*128)/256, 256>>>(x);                                 // 1
    k_pool4<<<(BB*CL*64*64)/256, 256>>>(x);                                   // 2
    k_pool8<<<(BB*CL*32*32)/256, 256>>>(x);                                   // 3
    k_dwall<<<(N_DW0+N_DW1+N_DW2+N_DW3)/256, 256>>>(x, wdw, bdw);             // 4
    fused_mma<<<1024, NTHR, SMEM_REQ>>>(x, bf1, bf2, bf3, out);               // 5
}

// round 6
// speedup vs baseline: 1.5730x; 1.5730x over previous
#include <cuda_runtime.h>
#include <cuda_bf16.h>
#include <math.h>
#include <stdint.h>

#define BB  8
#define DIM 128
#define CL  32
#define HH  256
#define WW  256

#define APITCH 136            // bf16 elems per row of weight images / A (K padded)
#define APB    (APITCH*2)     // 272 B rows: 17*16 -> ldmatrix-aligned, conflict-free
#define WPB    144            // W half-buffer pitch: 9*16 B, conflict-free

// ---------------- device scratch ----------------
__device__ float g_S0[BB*CL*HH*WW];
__device__ float g_P1[BB*CL*128*128];
__device__ float g_D1[BB*CL*128*128];
__device__ float g_P2[BB*CL*64*64];
__device__ float g_D2[BB*CL*64*64];
__device__ float g_P3[BB*CL*32*32];
__device__ float g_D3[BB*CL*32*32];

// weight images: shuffle-folded, bf16 hi/lo split, [N][APITCH]
__device__ __align__(16) __nv_bfloat16 g_W1h[64*APITCH];
__device__ __align__(16) __nv_bfloat16 g_W1l[64*APITCH];
__device__ __align__(16) __nv_bfloat16 g_W2h[96*APITCH];
__device__ __align__(16) __nv_bfloat16 g_W2l[96*APITCH];
__device__ __align__(16) __nv_bfloat16 g_W3h[128*APITCH];
__device__ __align__(16) __nv_bfloat16 g_W3l[128*APITCH];

// ---------------- smem layout (fused kernel): 104 KB -> 2 CTAs/SM ----------------
#define OFF_AHI 0
#define OFF_ALO 34816
#define OFF_WH  69632
#define OFF_WL  88064
#define SMEM_REQ 106496

// ---------------- asm helpers ----------------
__device__ __forceinline__ uint32_t smem_u32(const void* p) {
    uint32_t a;
    asm("{ .reg .u64 t; cvta.to.shared.u64 t, %1; cvt.u32.u64 %0, t; }" : "=r"(a) : "l"(p));
    return a;
}
__device__ __forceinline__ void ldsm_x4(uint32_t r[4], uint32_t addr) {
    asm volatile("ldmatrix.sync.aligned.m8n8.x4.shared.b16 {%0,%1,%2,%3}, [%4];"
        : "=r"(r[0]), "=r"(r[1]), "=r"(r[2]), "=r"(r[3]) : "r"(addr));
}
__device__ __forceinline__ void ldsm_x2(uint32_t& r0, uint32_t& r1, uint32_t addr) {
    asm volatile("ldmatrix.sync.aligned.m8n8.x2.shared.b16 {%0,%1}, [%2];"
        : "=r"(r0), "=r"(r1) : "r"(addr));
}
__device__ __forceinline__ void mma16816(float d[4], const uint32_t a[4], uint32_t b0, uint32_t b1) {
    asm volatile("mma.sync.aligned.m16n8k16.row.col.f32.bf16.bf16.f32 "
        "{%0,%1,%2,%3}, {%4,%5,%6,%7}, {%8,%9}, {%0,%1,%2,%3};"
        : "+f"(d[0]), "+f"(d[1]), "+f"(d[2]), "+f"(d[3])
        : "r"(a[0]), "r"(a[1]), "r"(a[2]), "r"(a[3]), "r"(b0), "r"(b1));
}
__device__ __forceinline__ void sts16(uint32_t addr, uint16_t v) {
    asm volatile("st.shared.b16 [%0], %1;" :: "r"(addr), "h"(v) : "memory");
}
__device__ __forceinline__ void sts32(uint32_t addr, uint32_t v) {
    asm volatile("st.shared.b32 [%0], %1;" :: "r"(addr), "r"(v) : "memory");
}
__device__ __forceinline__ void sts128(uint32_t addr, uint4 v) {
    asm volatile("st.shared.v4.b32 [%0], {%1,%2,%3,%4};"
        :: "r"(addr), "r"(v.x), "r"(v.y), "r"(v.z), "r"(v.w) : "memory");
}
__device__ __forceinline__ void lds128(float& a, float& b, float& c, float& d, uint32_t addr) {
    asm volatile("ld.shared.v4.f32 {%0,%1,%2,%3}, [%4];"
        : "=f"(a), "=f"(b), "=f"(c), "=f"(d) : "r"(addr));
}
__device__ __forceinline__ void splitf(float v, uint16_t& h, uint16_t& l) {
    __nv_bfloat16 hb = __float2bfloat16(v);
    __nv_bfloat16 lb = __float2bfloat16(v - __bfloat162float(hb));
    h = __bfloat16_as_ushort(hb);
    l = __bfloat16_as_ushort(lb);
}

// ---------------- weight prep ----------------
__global__ void k_prep(const float* __restrict__ w1, const float* __restrict__ w2,
                       const float* __restrict__ w3)
{
    int t = blockIdx.x * blockDim.x + threadIdx.x;
    float w; __nv_bfloat16 *ph, *pl; int r, k;
    if (t < 64*64) {
        r = t >> 6; k = t & 63;
        w = w1[(r << 6) + ((k & 7) << 3) + (k >> 3)];
        ph = g_W1h; pl = g_W1l;
    } else if (t < 64*64 + 96*96) {
        int u = t - 64*64; r = u / 96; k = u % 96;
        w = w2[r*96 + (k % 12)*8 + k/12];
        ph = g_W2h; pl = g_W2l;
    } else if (t < 64*64 + 96*96 + 128*128) {
        int u = t - 64*64 - 96*96; r = u >> 7; k = u & 127;
        w = w3[(r << 7) + ((k & 15) << 3) + (k >> 4)];
        ph = g_W3h; pl = g_W3l;
    } else return;
    __nv_bfloat16 hb = __float2bfloat16(w);
    __nv_bfloat16 lb = __float2bfloat16(w - __bfloat162float(hb));
    ph[r*APITCH + k] = hb;
    pl[r*APITCH + k] = lb;
}

// ---------------- pools ----------------
template<int KK>
__device__ __forceinline__ void pool_impl(const float* __restrict__ x, int lvl,
                                          float* __restrict__ out)
{
    const int HO = HH / KK;
    int idx = blockIdx.x * blockDim.x + threadIdx.x;
    if (idx >= BB*CL*HO*HO) return;
    int xo = idx % HO;
    int yo = (idx / HO) % HO;
    int c  = (idx / (HO*HO)) % CL;
    int b  = idx / (HO*HO*CL);
    const float* p = x + (((size_t)b*DIM + lvl*CL + c)*HH + (size_t)yo*KK)*WW + (size_t)xo*KK;
    float m = -3.402823466e38f;
    #pragma unroll
    for (int dy = 0; dy < KK; dy++)
        #pragma unroll
        for (int dx = 0; dx < KK; dx++)
            m = fmaxf(m, p[dy*WW + dx]);
    out[idx] = m;
}
__global__ void k_pool2(const float* __restrict__ x){ pool_impl<2>(x, 1, g_P1); }
__global__ void k_pool4(const float* __restrict__ x){ pool_impl<4>(x, 2, g_P2); }
__global__ void k_pool8(const float* __restrict__ x){ pool_impl<8>(x, 3, g_P3); }

// ---------------- depthwise 3x3 (all levels, one kernel) ----------------
__device__ __forceinline__ void dw_one(const float* __restrict__ in, float* __restrict__ out,
                                       const float* __restrict__ w_dw, const float* __restrict__ b_dw,
                                       int lvl, int S, bool from_x, int idx)
{
    int xx = idx % S;
    int yy = (idx / S) % S;
    int c  = (idx / (S*S)) % CL;
    int b  = idx / (S*S*CL);
    const float* ip = from_x ? in + ((size_t)b*DIM + lvl*CL + c) * (size_t)(S*S)
                             : in + ((size_t)b*CL + c) * (size_t)(S*S);
    const float* wp = w_dw + (lvl*CL + c) * 9;
    float acc = b_dw[lvl*CL + c];
    #pragma unroll
    for (int ky = 0; ky < 3; ky++) {
        int iy = yy + ky - 1;
        if ((unsigned)iy >= (unsigned)S) continue;
        #pragma unroll
        for (int kx = 0; kx < 3; kx++) {
            int ix = xx + kx - 1;
            if ((unsigned)ix >= (unsigned)S) continue;
            acc = fmaf(wp[ky*3 + kx], ip[iy*S + ix], acc);
        }
    }
    out[idx] = acc;
}

#define N_DW0 (BB*CL*256*256)
#define N_DW1 (BB*CL*128*128)
#define N_DW2 (BB*CL*64*64)
#define N_DW3 (BB*CL*32*32)
__global__ void k_dwall(const float* __restrict__ x, const float* __restrict__ w,
                        const float* __restrict__ b)
{
    int idx = blockIdx.x * blockDim.x + threadIdx.x;
    if (idx < N_DW0) { dw_one(x, g_S0, w, b, 0, 256, true, idx); return; }
    idx -= N_DW0;
    if (idx < N_DW1) { dw_one(g_P1, g_D1, w, b, 1, 128, false, idx); return; }
    idx -= N_DW1;
    if (idx < N_DW2) { dw_one(g_P2, g_D2, w, b, 2, 64, false, idx); return; }
    idx -= N_DW2;
    if (idx < N_DW3) { dw_one(g_P3, g_D3, w, b, 3, 32, false, idx); return; }
}

// ---------------- W half loader: gmem (L2-hot) -> smem ----------------
// copies cols [coff, coff+cbytes) of each of N rows (pitch 272B src, 144B dst)
__device__ __forceinline__ void load_whalf(uint32_t base,
                                           const __nv_bfloat16* __restrict__ gh,
                                           const __nv_bfloat16* __restrict__ gl,
                                           int N, int coff, int cbytes, int tid)
{
    int chunks = cbytes >> 4;
    int total = N * chunks;
    for (int i = tid; i < total; i += 512) {
        int r = i / chunks, c = (i - r*chunks) << 4;
        uint4 vh = *(const uint4*)((const char*)gh + r*APB + coff + c);
        uint4 vl = *(const uint4*)((const char*)gl + r*APB + coff + c);
        uint32_t d = base + (uint32_t)r*WPB + c;
        sts128(d + OFF_WH, vh);
        sts128(d + OFF_WL, vl);
    }
}

// ---------------- GEMM half-stage (warp-level mma) ----------------
// 16 warps: grid 4(M) x 4(N). Warp tile: 32 px x NT*8 out ch. KT k-steps of 16.
// Reads A cols [kcoff_bytes ...], W from the shared half buffer (pitch WPB).
template<int NT, int KT>
__device__ __forceinline__ void run_half(uint32_t base, int wm, int wn, int lane,
                                         float acc[2][4][4], int kcoff)
{
    const int mbase = wm * 32;
    const int nbase = wn * NT * 8;
    const uint32_t a_off = (uint32_t)(mbase + (lane & 15)) * APB + ((lane >> 4) << 4) + kcoff;
    const uint32_t b_off = (uint32_t)(nbase + (lane & 7)) * WPB + (((lane >> 3) & 1) << 4);
    const uint32_t AHI = base + OFF_AHI + a_off;
    const uint32_t ALO = base + OFF_ALO + a_off;
    const uint32_t WH  = base + OFF_WH  + b_off;
    const uint32_t WL  = base + OFF_WL  + b_off;

    #pragma unroll
    for (int kt = 0; kt < KT; kt++) {
        uint32_t ah[2][4], al[2][4];
        #pragma unroll
        for (int mt = 0; mt < 2; mt++) {
            ldsm_x4(ah[mt], AHI + mt*16*APB + kt*32);
            ldsm_x4(al[mt], ALO + mt*16*APB + kt*32);
        }
        #pragma unroll
        for (int nt = 0; nt < NT; nt++) {
            uint32_t bh0, bh1, bl0, bl1;
            ldsm_x2(bh0, bh1, WH + nt*8*WPB + kt*32);
            ldsm_x2(bl0, bl1, WL + nt*8*WPB + kt*32);
            #pragma unroll
            for (int mt = 0; mt < 2; mt++) {
                mma16816(acc[mt][nt], ah[mt], bh0, bh1);
                mma16816(acc[mt][nt], al[mt], bh0, bh1);
                mma16816(acc[mt][nt], ah[mt], bl0, bl1);
            }
        }
    }
}

template<int NT>
__device__ __forceinline__ void zero_acc(float acc[2][4][4])
{
    #pragma unroll
    for (int mt = 0; mt < 2; mt++)
        #pragma unroll
        for (int nt = 0; nt < NT; nt++)
            #pragma unroll
            for (int i = 0; i < 4; i++) acc[mt][nt][i] = 0.0f;
}

template<int NT>
__device__ __forceinline__ void writeback(uint32_t base, const float* __restrict__ bias,
                                          int wm, int wn, int lane, float acc[2][4][4])
{
    const int mbase = wm * 32;
    const int nbase = wn * NT * 8;
    #pragma unroll
    for (int mt = 0; mt < 2; mt++) {
        int p0 = mbase + mt*16 + (lane >> 2);
        #pragma unroll
        for (int nt = 0; nt < NT; nt++) {
            int o = nbase + nt*8 + (lane & 3)*2;
            float b0 = __ldg(&bias[o]), b1 = __ldg(&bias[o+1]);
            uint16_t h0, l0, h1, l1;
            splitf(acc[mt][nt][0] + b0, h0, l0);
            splitf(acc[mt][nt][1] + b1, h1, l1);
            uint32_t addr = base + (uint32_t)p0*APB + o*2;
            sts32(addr + OFF_AHI, (uint32_t)h0 | ((uint32_t)h1 << 16));
            sts32(addr + OFF_ALO, (uint32_t)l0 | ((uint32_t)l1 << 16));
            splitf(acc[mt][nt][2] + b0, h0, l0);
            splitf(acc[mt][nt][3] + b1, h1, l1);
            addr += 8*APB;
            sts32(addr + OFF_AHI, (uint32_t)h0 | ((uint32_t)h1 << 16));
            sts32(addr + OFF_ALO, (uint32_t)l0 | ((uint32_t)l1 << 16));
        }
    }
}

// ---------------- fused kernel: 512 threads, 16 warps, 2 CTAs/SM ----------------
#define TPC 4
#define NTHR 512
__global__ __launch_bounds__(NTHR, 2)
void fused_mma(const float* __restrict__ x,
               const float* __restrict__ bf1, const float* __restrict__ bf2,
               const float* __restrict__ bf3, float* __restrict__ out)
{
    extern __shared__ __align__(16) unsigned char sm[];
    const uint32_t base = smem_u32(sm);
    const int tid = threadIdx.x;
    const int lane = tid & 31, wid = tid >> 5;
    const int wm = wid >> 2, wn = wid & 3;

    float acc[2][4][4];

    for (int t = 0; t < TPC; t++) {
        int tile = blockIdx.x * TPC + t;
        int b = tile >> 9;
        int rem = (tile & 511) * 128;

        __syncthreads();   // A region free (prev tile epilogue done)

        // ---- build A (128 px x 128 ch, bf16 split) ----
        for (int i = tid; i < 128*128; i += NTHR) {
            int ch = i >> 7, p = i & 127;
            int r = rem + p;
            int y = r >> 8, xx = r & 255;
            float v;
            if (ch < 32)      v = g_S0[((b*32 + ch) << 16) + r];
            else if (ch < 64) v = g_D1[(b*32 + ch-32)*16384 + (y>>1)*128 + (xx>>1)];
            else if (ch < 96) v = g_D2[(b*32 + ch-64)*4096  + (y>>2)*64  + (xx>>2)];
            else              v = g_D3[(b*32 + ch-96)*1024  + (y>>3)*32  + (xx>>3)];
            uint16_t h, l;
            splitf(v, h, l);
            uint32_t addr = base + (uint32_t)p*APB + ch*2;
            sts16(addr + OFF_AHI, h);
            sts16(addr + OFF_ALO, l);
        }
        // also serves as "W buffer free" barrier for stage-1 load below
        __syncthreads();

        // ---- stage 1: K=64 (one half) ----
        load_whalf(base, g_W1h, g_W1l, 64, 0, 128, tid);
        __syncthreads();
        zero_acc<2>(acc);
        run_half<2, 4>(base, wm, wn, lane, acc, 0);
        __syncthreads();                 // reads done before A overwrite
        writeback<2>(base, bf1, wm, wn, lane, acc);
        __syncthreads();                 // writeback visible + W buffer free

        // ---- stage 2: K=96 (64 + 32) ----
        load_whalf(base, g_W2h, g_W2l, 96, 0, 128, tid);
        __syncthreads();
        zero_acc<3>(acc);
        run_half<3, 4>(base, wm, wn, lane, acc, 0);
        __syncthreads();                 // W free
        load_whalf(base, g_W2h, g_W2l, 96, 128, 64, tid);
        __syncthreads();
        run_half<3, 2>(base, wm, wn, lane, acc, 128);
        __syncthreads();
        writeback<3>(base, bf2, wm, wn, lane, acc);
        __syncthreads();

        // ---- stage 3: K=128 (64 + 64) ----
        load_whalf(base, g_W3h, g_W3l, 128, 0, 128, tid);
        __syncthreads();
        zero_acc<4>(acc);
        run_half<4, 4>(base, wm, wn, lane, acc, 0);
        __syncthreads();
        load_whalf(base, g_W3h, g_W3l, 128, 128, 128, tid);
        __syncthreads();
        run_half<4, 4>(base, wm, wn, lane, acc, 128);
        __syncthreads();                 // A reads done; epilogue reuses A region

        // ---- epilogue: gelu -> smem (stride 132 floats), coalesced *x -> out ----
        {
            const int mbase = wm * 32, nbase = wn * 32;
            #pragma unroll
            for (int mt = 0; mt < 2; mt++) {
                int p0 = mbase + mt*16 + (lane >> 2);
                #pragma unroll
                for (int nt = 0; nt < 4; nt++) {
                    int o = nbase + nt*8 + (lane & 3)*2;
                    float b0 = __ldg(&bf3[o]), b1 = __ldg(&bf3[o+1]);
                    #pragma unroll
                    for (int hrow = 0; hrow < 2; hrow++) {
                        float v0 = acc[mt][nt][2*hrow+0] + b0;
                        float v1 = acc[mt][nt][2*hrow+1] + b1;
                        float g0 = 0.5f * v0 * (1.0f + erff(v0 * 0.70710678118654752f));
                        float g1 = 0.5f * v1 * (1.0f + erff(v1 * 0.70710678118654752f));
                        int p = p0 + hrow*8;
                        sts32(base + ((uint32_t)o    *132 + p)*4, __float_as_uint(g0));
                        sts32(base + ((uint32_t)(o+1)*132 + p)*4, __float_as_uint(g1));
                    }
                }
            }
        }
        __syncthreads();
        for (int i = tid; i < 128*32; i += NTHR) {
            int ch = i >> 5, g4 = (i & 31) * 4;
            size_t gi = ((size_t)(b*128 + ch) << 16) + rem + g4;
            float v0, v1, v2, v3;
            lds128(v0, v1, v2, v3, base + ((uint32_t)ch*132 + g4)*4);
            float4 xv = *(const float4*)&x[gi];
            float4 o4;
            o4.x = v0 * xv.x; o4.y = v1 * xv.y; o4.z = v2 * xv.z; o4.w = v3 * xv.w;
            *(float4*)&out[gi] = o4;
        }
    }
}

// ---------------- launch ----------------
extern "C" void kernel_launch(void* const* d_in, const int* in_sizes, int n_in,
                              void* d_out, int out_size)
{
    const float* x   = (const float*)d_in[0];
    const float* wdw = (const float*)d_in[1];
    const float* bdw = (const float*)d_in[2];
    const float* wf1 = (const float*)d_in[3];
    const float* bf1 = (const float*)d_in[4];
    const float* wf2 = (const float*)d_in[5];
    const float* bf2 = (const float*)d_in[6];
    const float* wf3 = (const float*)d_in[7];
    const float* bf3 = (const float*)d_in[8];
    float* out = (float*)d_out;
    (void)in_sizes; (void)n_in; (void)out_size;

    cudaFuncSetAttribute(fused_mma, cudaFuncAttributeMaxDynamicSharedMemorySize, SMEM_REQ);

    k_prep<<<(64*64 + 96*96 + 128*128 + 255)/256, 256>>>(wf1, wf2, wf3);     // 0
    k_pool2<<<(BB*CL*128*128)/256, 256>>>(x);                                 // 1
    k_pool4<<<(BB*CL*64*64)/256, 256>>>(x);                                   // 2
    k_pool8<<<(BB*CL*32*32)/256, 256>>>(x);                                   // 3
    k_dwall<<<(N_DW0+N_DW1+N_DW2+N_DW3)/256, 256>>>(x, wdw, bdw);             // 4
    fused_mma<<<1024, NTHR, SMEM_REQ>>>(x, bf1, bf2, bf3, out);               // 5
}